// round 11
// baseline (speedup 1.0000x reference)
#include <cuda_runtime.h>
#include <cuda_bf16.h>
#include <stdint.h>
#include <math.h>

#define NN 100000
#define NE 1600000
#define FIN 512
#define D1 64
#define D2 256
#define SCAN_B 1024
#define SCAN_NB ((NN + SCAN_B - 1) / SCAN_B)

__device__ float    g_dinv[NN];
__device__ int      g_cnt[NN];
__device__ int      g_tmp[NN];
__device__ int      g_bsum[SCAN_NB];
__device__ int      g_rowstart[NN + 1];
__device__ int      g_csrsrc[NE];
__device__ uint4    g_bfrag[8192];             // packed W1 b-frags
__device__ uint4    g_bfrag2[4096];            // packed W2 b-frags
__device__ uint32_t g_xw1[(size_t)NN * 32];    // bf16x2, dinv-scaled x@W1
__device__ uint32_t g_h1 [(size_t)NN * 32];    // bf16x2, dinv-scaled relu(A xw1 + b1)
__device__ float    g_z0 [NN];                 // dinv-scaled h2@W3

// ---------------- bf16 helpers ----------------
__device__ __forceinline__ uint32_t pkbf(float a, float b) {
    __nv_bfloat162 h = __floats2bfloat162_rn(a, b);
    return *(uint32_t*)&h;
}
__device__ __forceinline__ float2 upbf(uint32_t v) {
    __nv_bfloat162 h = *(__nv_bfloat162*)&v;
    return __bfloat1622float2(h);
}
__device__ __forceinline__ float bfres(float f) {
    return f - __bfloat162float(__float2bfloat16(f));
}
__device__ __forceinline__ void mma_bf16(float* c, const uint32_t* a, uint32_t b0, uint32_t b1) {
    asm("mma.sync.aligned.m16n8k16.row.col.f32.bf16.bf16.f32 "
        "{%0,%1,%2,%3}, {%4,%5,%6,%7}, {%8,%9}, {%0,%1,%2,%3};"
        : "+f"(c[0]), "+f"(c[1]), "+f"(c[2]), "+f"(c[3])
        : "r"(a[0]), "r"(a[1]), "r"(a[2]), "r"(a[3]), "r"(b0), "r"(b1));
}

// ---------------- CSR build ----------------
__global__ void k_clear() {
    int i = blockIdx.x * blockDim.x + threadIdx.x;
    if (i < NN) g_cnt[i] = 0;
}
__global__ void k_hist(const int* __restrict__ dst) {
    int e = blockIdx.x * blockDim.x + threadIdx.x;
    if (e < NE) atomicAdd(&g_cnt[dst[e]], 1);
}
__global__ void k_dinv() {
    int i = blockIdx.x * blockDim.x + threadIdx.x;
    if (i < NN) g_dinv[i] = rsqrtf((float)g_cnt[i] + 1.0f);
}
__global__ __launch_bounds__(SCAN_B) void k_scan1() {
    __shared__ int sh[SCAN_B];
    int t = threadIdx.x;
    int i = blockIdx.x * SCAN_B + t;
    sh[t] = (i < NN) ? g_cnt[i] : 0;
    __syncthreads();
#pragma unroll
    for (int off = 1; off < SCAN_B; off <<= 1) {
        int v = (t >= off) ? sh[t - off] : 0;
        __syncthreads();
        sh[t] += v;
        __syncthreads();
    }
    if (i < NN) g_tmp[i] = sh[t];
    if (t == SCAN_B - 1) g_bsum[blockIdx.x] = sh[t];
}
__global__ __launch_bounds__(128) void k_scan2() {
    __shared__ int sh[128];
    int t = threadIdx.x;
    int v0 = (t < SCAN_NB) ? g_bsum[t] : 0;
    sh[t] = v0;
    __syncthreads();
#pragma unroll
    for (int off = 1; off < 128; off <<= 1) {
        int v = (t >= off) ? sh[t - off] : 0;
        __syncthreads();
        sh[t] += v;
        __syncthreads();
    }
    if (t < SCAN_NB) g_bsum[t] = sh[t] - v0;
}
__global__ void k_scan3() {
    int i = blockIdx.x * blockDim.x + threadIdx.x;
    if (i < NN) {
        g_rowstart[i + 1] = g_tmp[i] + g_bsum[i >> 10];
        if (i == 0) g_rowstart[0] = 0;
        g_cnt[i] = 0;
    }
}
__global__ void k_fill(const int* __restrict__ src, const int* __restrict__ dst) {
    int e = blockIdx.x * blockDim.x + threadIdx.x;
    if (e < NE) {
        int d = dst[e];
        int pos = g_rowstart[d] + atomicAdd(&g_cnt[d], 1);
        g_csrsrc[pos] = src[e];
    }
}

// ---------------- pack W1 [512,64] + W2 [64,256] into mma b-fragments ----------------
__global__ void k_packW(const float* __restrict__ B1, const float* __restrict__ B2) {
    int e = blockIdx.x * blockDim.x + threadIdx.x;
    if (e < 8192) {
        int l = e & 31, j = (e >> 5) & 7, s = e >> 8;
        int g = l >> 2, t = l & 3;
        int n = 8 * j + g;
        int k = 16 * s + 2 * t;
        float f0 = B1[(size_t)k * 64 + n];
        float f1 = B1[(size_t)(k + 1) * 64 + n];
        float f2 = B1[(size_t)(k + 8) * 64 + n];
        float f3 = B1[(size_t)(k + 9) * 64 + n];
        g_bfrag[e] = make_uint4(pkbf(f0, f1), pkbf(f2, f3),
                                pkbf(bfres(f0), bfres(f1)), pkbf(bfres(f2), bfres(f3)));
    } else if (e < 8192 + 4096) {
        int e2 = e - 8192;
        int l = e2 & 31, j = (e2 >> 5) & 31, s = e2 >> 10;
        int g = l >> 2, t = l & 3;
        int n = 8 * j + g;
        int k = 16 * s + 2 * t;
        float f0 = B2[(size_t)k * D2 + n];
        float f1 = B2[(size_t)(k + 1) * D2 + n];
        float f2 = B2[(size_t)(k + 8) * D2 + n];
        float f3 = B2[(size_t)(k + 9) * D2 + n];
        g_bfrag2[e2] = make_uint4(pkbf(f0, f1), pkbf(f2, f3),
                                  pkbf(bfres(f0), bfres(f1)), pkbf(bfres(f2), bfres(f3)));
    }
}

// ---------------- GEMM1 via mma.sync bf16 split-3; writes dinv-scaled bf16x2 ----------------
#define G1A_STRIDE 36
#define G1_SMEM_BYTES (2 * 256 * 72 * 2)
__global__ __launch_bounds__(256) void k_gemm1_mma(const float* __restrict__ A,
                                                   uint32_t* __restrict__ C) {
    extern __shared__ char smem[];
    uint32_t* Ah = (uint32_t*)smem;
    uint32_t* Al = (uint32_t*)(smem + 256 * 72 * 2);
    int tid  = threadIdx.x;
    int lane = tid & 31;
    int w    = tid >> 5;
    int g    = lane >> 2;
    int t    = lane & 3;
    int bm   = blockIdx.x * 256;

    float acc[2][8][4];
#pragma unroll
    for (int m = 0; m < 2; m++)
#pragma unroll
        for (int j = 0; j < 8; j++)
#pragma unroll
            for (int q = 0; q < 4; q++) acc[m][j][q] = 0.f;

    int lr = tid >> 4;
    int c4 = (tid & 15) * 4;

    for (int ch = 0; ch < 8; ch++) {
        int k0 = ch * 64;
#pragma unroll
        for (int i = 0; i < 16; i++) {
            int row  = lr + 16 * i;
            int grow = bm + row;
            float4 v = (grow < NN) ? *(const float4*)(A + (size_t)grow * FIN + k0 + c4)
                                   : make_float4(0.f, 0.f, 0.f, 0.f);
            int idx = row * G1A_STRIDE + (c4 >> 1);
            *(uint2*)&Ah[idx] = make_uint2(pkbf(v.x, v.y), pkbf(v.z, v.w));
            *(uint2*)&Al[idx] = make_uint2(pkbf(bfres(v.x), bfres(v.y)), pkbf(bfres(v.z), bfres(v.w)));
        }
        __syncthreads();
#pragma unroll
        for (int s4 = 0; s4 < 4; s4++) {
            int kk = s4 * 16;
            int gs = ch * 4 + s4;
            uint32_t ah[2][4], al[2][4];
#pragma unroll
            for (int m = 0; m < 2; m++) {
                int r0 = w * 32 + m * 16 + g;
                int kc = (kk + 2 * t) >> 1;
                ah[m][0] = Ah[r0 * G1A_STRIDE + kc];
                ah[m][1] = Ah[(r0 + 8) * G1A_STRIDE + kc];
                ah[m][2] = Ah[r0 * G1A_STRIDE + kc + 4];
                ah[m][3] = Ah[(r0 + 8) * G1A_STRIDE + kc + 4];
                al[m][0] = Al[r0 * G1A_STRIDE + kc];
                al[m][1] = Al[(r0 + 8) * G1A_STRIDE + kc];
                al[m][2] = Al[r0 * G1A_STRIDE + kc + 4];
                al[m][3] = Al[(r0 + 8) * G1A_STRIDE + kc + 4];
            }
#pragma unroll
            for (int j = 0; j < 8; j++) {
                uint4 bf4 = __ldg(&g_bfrag[(gs * 8 + j) * 32 + lane]);
#pragma unroll
                for (int m = 0; m < 2; m++) {
                    mma_bf16(acc[m][j], ah[m], bf4.x, bf4.y);
                    mma_bf16(acc[m][j], ah[m], bf4.z, bf4.w);
                    mma_bf16(acc[m][j], al[m], bf4.x, bf4.y);
                }
            }
        }
        __syncthreads();
    }
#pragma unroll
    for (int m = 0; m < 2; m++) {
        int row = bm + w * 32 + m * 16 + g;
        float d0 = (row < NN)     ? g_dinv[row]     : 0.f;
        float d1 = (row + 8 < NN) ? g_dinv[row + 8] : 0.f;
#pragma unroll
        for (int j = 0; j < 8; j++) {
            int cp = 4 * j + t;
            if (row < NN)
                C[(size_t)row * 32 + cp] = pkbf(acc[m][j][0] * d0, acc[m][j][1] * d0);
            if (row + 8 < NN)
                C[(size_t)(row + 8) * 32 + cp] = pkbf(acc[m][j][2] * d1, acc[m][j][3] * d1);
        }
    }
}

// ---------------- gather 1: bf16 in -> bf16 out (relu+bias, dinv^2 scaling), unroll 8 ----
__global__ __launch_bounds__(256) void k_gather_bf2bf(const uint32_t* __restrict__ in,
                                                      uint32_t* __restrict__ out,
                                                      const float* __restrict__ bias) {
    int node = (blockIdx.x * blockDim.x + threadIdx.x) >> 5;
    if (node >= NN) return;
    int lane = threadIdx.x & 31;
    float dd = g_dinv[node];
    float2 self = upbf(in[node * 32 + lane]);
    float ax = self.x, ay = self.y;
    int e   = g_rowstart[node];
    int end = g_rowstart[node + 1];
    for (; e + 7 < end; e += 8) {
        int s[8];
#pragma unroll
        for (int q = 0; q < 8; q++) s[q] = __ldg(&g_csrsrc[e + q]);
        float2 v[8];
#pragma unroll
        for (int q = 0; q < 8; q++) v[q] = upbf(__ldg(&in[s[q] * 32 + lane]));
#pragma unroll
        for (int q = 0; q < 8; q++) { ax += v[q].x; ay += v[q].y; }
    }
    for (; e < end; e++) {
        float2 v = upbf(__ldg(&in[__ldg(&g_csrsrc[e]) * 32 + lane]));
        ax += v.x;
        ay += v.y;
    }
    float2 bb = ((const float2*)bias)[lane];
    ax = fmaxf(ax * dd + bb.x, 0.f) * dd;
    ay = fmaxf(ay * dd + bb.y, 0.f) * dd;
    out[node * 32 + lane] = pkbf(ax, ay);
}

// ---------------- GEMM2 fused with gather2 + W3 matvec ----------------
// Each block: 256 rows. Phase 1: gather A h1 for own rows straight into smem bf16 staging.
// Phase 2: mma over 4 n-chunks, relu+bias, dot W3, write dinv-scaled z0.
__global__ __launch_bounds__(256) void k_gemm2_fused(const uint32_t* __restrict__ h1,
                                                     const float* __restrict__ bias,
                                                     const float* __restrict__ W3) {
    extern __shared__ char smem[];
    uint32_t* Ah = (uint32_t*)smem;
    uint32_t* Al = (uint32_t*)(smem + 256 * 72 * 2);
    __shared__ float zpart[256];
    int tid  = threadIdx.x;
    int lane = tid & 31;
    int w    = tid >> 5;
    int g    = lane >> 2;
    int t    = lane & 3;
    int bm   = blockIdx.x * 256;
    zpart[tid] = 0.f;

    // ---- phase 1: gather own 256 rows (warp w handles rows w*32 .. w*32+31) ----
    for (int i = 0; i < 32; i++) {
        int row  = w * 32 + i;
        int node = bm + row;
        float ax = 0.f, ay = 0.f;
        if (node < NN) {
            float dd = g_dinv[node];
            float2 self = upbf(h1[node * 32 + lane]);
            ax = self.x; ay = self.y;
            int e   = g_rowstart[node];
            int end = g_rowstart[node + 1];
            for (; e + 7 < end; e += 8) {
                int s[8];
#pragma unroll
                for (int q = 0; q < 8; q++) s[q] = __ldg(&g_csrsrc[e + q]);
                float2 v[8];
#pragma unroll
                for (int q = 0; q < 8; q++) v[q] = upbf(__ldg(&h1[s[q] * 32 + lane]));
#pragma unroll
                for (int q = 0; q < 8; q++) { ax += v[q].x; ay += v[q].y; }
            }
            for (; e < end; e++) {
                float2 v = upbf(__ldg(&h1[__ldg(&g_csrsrc[e]) * 32 + lane]));
                ax += v.x;
                ay += v.y;
            }
            ax *= dd; ay *= dd;
        }
        Ah[row * G1A_STRIDE + lane] = pkbf(ax, ay);
        Al[row * G1A_STRIDE + lane] = pkbf(bfres(ax), bfres(ay));
    }
    __syncthreads();

    // ---- phase 2: mma over 4 n-chunks ----
    for (int c = 0; c < 4; c++) {
        float acc[2][8][4];
#pragma unroll
        for (int m = 0; m < 2; m++)
#pragma unroll
            for (int j = 0; j < 8; j++)
#pragma unroll
                for (int q = 0; q < 4; q++) acc[m][j][q] = 0.f;
#pragma unroll
        for (int s4 = 0; s4 < 4; s4++) {
            int kk = s4 * 16;
            uint32_t ah[2][4], al[2][4];
#pragma unroll
            for (int m = 0; m < 2; m++) {
                int r0 = w * 32 + m * 16 + g;
                int kc = (kk + 2 * t) >> 1;
                ah[m][0] = Ah[r0 * G1A_STRIDE + kc];
                ah[m][1] = Ah[(r0 + 8) * G1A_STRIDE + kc];
                ah[m][2] = Ah[r0 * G1A_STRIDE + kc + 4];
                ah[m][3] = Ah[(r0 + 8) * G1A_STRIDE + kc + 4];
                al[m][0] = Al[r0 * G1A_STRIDE + kc];
                al[m][1] = Al[(r0 + 8) * G1A_STRIDE + kc];
                al[m][2] = Al[r0 * G1A_STRIDE + kc + 4];
                al[m][3] = Al[(r0 + 8) * G1A_STRIDE + kc + 4];
            }
#pragma unroll
            for (int j = 0; j < 8; j++) {
                uint4 bf4 = __ldg(&g_bfrag2[(s4 * 32 + c * 8 + j) * 32 + lane]);
#pragma unroll
                for (int m = 0; m < 2; m++) {
                    mma_bf16(acc[m][j], ah[m], bf4.x, bf4.y);
                    mma_bf16(acc[m][j], ah[m], bf4.z, bf4.w);
                    mma_bf16(acc[m][j], al[m], bf4.x, bf4.y);
                }
            }
        }
#pragma unroll
        for (int m = 0; m < 2; m++) {
            int rl0 = w * 32 + m * 16 + g;
            float s0 = 0.f, s1 = 0.f;
#pragma unroll
            for (int j = 0; j < 8; j++) {
                int col = c * 64 + 8 * j + 2 * t;
                float b0 = bias[col], b1 = bias[col + 1];
                float w0 = W3[col],  w1 = W3[col + 1];
                s0 += fmaxf(acc[m][j][0] + b0, 0.f) * w0 + fmaxf(acc[m][j][1] + b1, 0.f) * w1;
                s1 += fmaxf(acc[m][j][2] + b0, 0.f) * w0 + fmaxf(acc[m][j][3] + b1, 0.f) * w1;
            }
            atomicAdd(&zpart[rl0],     s0);
            atomicAdd(&zpart[rl0 + 8], s1);
        }
    }
    __syncthreads();
    int row = bm + tid;
    if (row < NN) g_z0[row] = zpart[tid] * g_dinv[row];
}

// ---------------- fused z aggregation + BCE loss (z0 pre-scaled) ----------------
__global__ void k_zero(float* out) {
    if (blockIdx.x == 0 && threadIdx.x == 0) out[0] = 0.f;
}
__global__ __launch_bounds__(256) void k_zagg_loss(const float* __restrict__ b3,
                                                   const float* __restrict__ y,
                                                   float* __restrict__ out) {
    __shared__ float red[256];
    int i = blockIdx.x * blockDim.x + threadIdx.x;
    float v = 0.f;
    if (i < NN) {
        float dd  = g_dinv[i];
        float acc = g_z0[i];
        int e = g_rowstart[i], end = g_rowstart[i + 1];
        for (; e + 7 < end; e += 8) {
            int s[8];
#pragma unroll
            for (int q = 0; q < 8; q++) s[q] = __ldg(&g_csrsrc[e + q]);
            float vv = 0.f;
#pragma unroll
            for (int q = 0; q < 8; q++) vv += __ldg(&g_z0[s[q]]);
            acc += vv;
        }
        for (; e < end; e++) acc += __ldg(&g_z0[__ldg(&g_csrsrc[e])]);
        float z = acc * dd + b3[0];
        float t = y[i];
        v = fmaxf(z, 0.f) - z * t + log1pf(expf(-fabsf(z)));
    }
    red[threadIdx.x] = v;
    __syncthreads();
    for (int s = 128; s > 0; s >>= 1) {
        if (threadIdx.x < s) red[threadIdx.x] += red[threadIdx.x + s];
        __syncthreads();
    }
    if (threadIdx.x == 0) atomicAdd(out, red[0] * (1.0f / NN));
}

// ---------------- launcher ----------------
static cudaStream_t g_s2 = 0;
static cudaEvent_t  g_evFork = 0, g_evJoin = 0;

extern "C" void kernel_launch(void* const* d_in, const int* in_sizes, int n_in,
                              void* d_out, int out_size) {
    const float* x  = (const float*)d_in[0];
    const int*   ei = (const int*)  d_in[1];
    const float* y  = (const float*)d_in[2];
    const float* W1 = (const float*)d_in[3];
    const float* b1 = (const float*)d_in[4];
    const float* W2 = (const float*)d_in[5];
    const float* b2 = (const float*)d_in[6];
    const float* W3 = (const float*)d_in[7];
    const float* b3 = (const float*)d_in[8];
    const int* src = ei;
    const int* dst = ei + NE;
    float* out = (float*)d_out;

    uint32_t *p_xw1, *p_h1;
    cudaGetSymbolAddress((void**)&p_xw1, g_xw1);
    cudaGetSymbolAddress((void**)&p_h1,  g_h1);

    cudaFuncSetAttribute(k_gemm1_mma,   cudaFuncAttributeMaxDynamicSharedMemorySize, G1_SMEM_BYTES);
    cudaFuncSetAttribute(k_gemm2_fused, cudaFuncAttributeMaxDynamicSharedMemorySize, G1_SMEM_BYTES);

    if (!g_s2) {
        cudaStreamCreateWithFlags(&g_s2, cudaStreamNonBlocking);
        cudaEventCreateWithFlags(&g_evFork, cudaEventDisableTiming);
        cudaEventCreateWithFlags(&g_evJoin, cudaEventDisableTiming);
    }

    const int T = 256;
    // ---- prefix on default stream: zero out + degree histogram + dinv ----
    k_zero <<<1, 32>>>(out);
    k_clear<<<(NN + T - 1) / T, T>>>();
    k_hist <<<(NE + T - 1) / T, T>>>(dst);
    k_dinv <<<(NN + T - 1) / T, T>>>();

    // ---- fork: CSR (scan+fill) on s2  ||  packW + gemm1 on default ----
    cudaEventRecord(g_evFork, 0);
    cudaStreamWaitEvent(g_s2, g_evFork, 0);
    k_scan1<<<SCAN_NB, SCAN_B, 0, g_s2>>>();
    k_scan2<<<1, 128, 0, g_s2>>>();
    k_scan3<<<(NN + T - 1) / T, T, 0, g_s2>>>();
    k_fill <<<(NE + T - 1) / T, T, 0, g_s2>>>(src, dst);
    cudaEventRecord(g_evJoin, g_s2);

    k_packW<<<48, 256>>>(W1, W2);
    k_gemm1_mma<<<(NN + 255) / 256, 256, G1_SMEM_BYTES>>>(x, p_xw1);

    // ---- join ----
    cudaStreamWaitEvent(0, g_evJoin, 0);

    // ---- layer 1 aggregate ----
    k_gather_bf2bf<<<(NN * 32 + T - 1) / T, T>>>(p_xw1, p_h1, b1);

    // ---- layer 2 (gather fused) + layer-3 matvec ----
    k_gemm2_fused<<<(NN + 255) / 256, 256, G1_SMEM_BYTES>>>(p_h1, b2, W3);

    // ---- z aggregation + loss ----
    k_zagg_loss<<<(NN + T - 1) / T, T>>>(b3, y, out);
}

// round 12
// speedup vs baseline: 1.4093x; 1.4093x over previous
#include <cuda_runtime.h>
#include <cuda_bf16.h>
#include <stdint.h>
#include <math.h>

#define NN 100000
#define NE 1600000
#define FIN 512
#define D1 64
#define D2 256
#define SCAN_B 1024
#define SCAN_NB ((NN + SCAN_B - 1) / SCAN_B)

__device__ float    g_dinv[NN];
__device__ int      g_cnt[NN];
__device__ int      g_tmp[NN];
__device__ int      g_bsum[SCAN_NB];
__device__ int      g_rowstart[NN + 1];
__device__ int      g_csrsrc[NE];
__device__ uint4    g_bfrag[8192];             // packed W1 b-frags
__device__ uint4    g_bfrag2[4096];            // packed W2 b-frags
__device__ uint32_t g_xw1[(size_t)NN * 32];    // bf16x2 x@W1 (unscaled, then dinv-scaled in place)
__device__ uint32_t g_h1 [(size_t)NN * 32];    // bf16x2, dinv-scaled relu(A xw1 + b1)
__device__ float    g_ah1[(size_t)NN * D1];    // A h1 (fp32)
__device__ float    g_z0 [NN];                 // dinv-scaled h2@W3

// ---------------- bf16 helpers ----------------
__device__ __forceinline__ uint32_t pkbf(float a, float b) {
    __nv_bfloat162 h = __floats2bfloat162_rn(a, b);
    return *(uint32_t*)&h;
}
__device__ __forceinline__ float2 upbf(uint32_t v) {
    __nv_bfloat162 h = *(__nv_bfloat162*)&v;
    return __bfloat1622float2(h);
}
__device__ __forceinline__ float bfres(float f) {
    return f - __bfloat162float(__float2bfloat16(f));
}
__device__ __forceinline__ void mma_bf16(float* c, const uint32_t* a, uint32_t b0, uint32_t b1) {
    asm("mma.sync.aligned.m16n8k16.row.col.f32.bf16.bf16.f32 "
        "{%0,%1,%2,%3}, {%4,%5,%6,%7}, {%8,%9}, {%0,%1,%2,%3};"
        : "+f"(c[0]), "+f"(c[1]), "+f"(c[2]), "+f"(c[3])
        : "r"(a[0]), "r"(a[1]), "r"(a[2]), "r"(a[3]), "r"(b0), "r"(b1));
}

// ---------------- CSR build ----------------
__global__ void k_clear() {
    int i = blockIdx.x * blockDim.x + threadIdx.x;
    if (i < NN) g_cnt[i] = 0;
}
__global__ void k_hist(const int* __restrict__ dst) {
    int e = blockIdx.x * blockDim.x + threadIdx.x;
    if (e < NE) atomicAdd(&g_cnt[dst[e]], 1);
}
__global__ void k_dinv() {
    int i = blockIdx.x * blockDim.x + threadIdx.x;
    if (i < NN) g_dinv[i] = rsqrtf((float)g_cnt[i] + 1.0f);
}
__global__ __launch_bounds__(SCAN_B) void k_scan1() {
    __shared__ int sh[SCAN_B];
    int t = threadIdx.x;
    int i = blockIdx.x * SCAN_B + t;
    sh[t] = (i < NN) ? g_cnt[i] : 0;
    __syncthreads();
#pragma unroll
    for (int off = 1; off < SCAN_B; off <<= 1) {
        int v = (t >= off) ? sh[t - off] : 0;
        __syncthreads();
        sh[t] += v;
        __syncthreads();
    }
    if (i < NN) g_tmp[i] = sh[t];
    if (t == SCAN_B - 1) g_bsum[blockIdx.x] = sh[t];
}
__global__ __launch_bounds__(128) void k_scan2() {
    __shared__ int sh[128];
    int t = threadIdx.x;
    int v0 = (t < SCAN_NB) ? g_bsum[t] : 0;
    sh[t] = v0;
    __syncthreads();
#pragma unroll
    for (int off = 1; off < 128; off <<= 1) {
        int v = (t >= off) ? sh[t - off] : 0;
        __syncthreads();
        sh[t] += v;
        __syncthreads();
    }
    if (t < SCAN_NB) g_bsum[t] = sh[t] - v0;
}
__global__ void k_scan3() {
    int i = blockIdx.x * blockDim.x + threadIdx.x;
    if (i < NN) {
        g_rowstart[i + 1] = g_tmp[i] + g_bsum[i >> 10];
        if (i == 0) g_rowstart[0] = 0;
        g_cnt[i] = 0;
    }
}
__global__ void k_fill(const int* __restrict__ src, const int* __restrict__ dst) {
    int e = blockIdx.x * blockDim.x + threadIdx.x;
    if (e < NE) {
        int d = dst[e];
        int pos = g_rowstart[d] + atomicAdd(&g_cnt[d], 1);
        g_csrsrc[pos] = src[e];
    }
}

// ---------------- pack W1 [512,64] + W2 [64,256] into mma b-fragments ----------------
__global__ void k_packW(const float* __restrict__ B1, const float* __restrict__ B2) {
    int e = blockIdx.x * blockDim.x + threadIdx.x;
    if (e < 8192) {
        int l = e & 31, j = (e >> 5) & 7, s = e >> 8;
        int g = l >> 2, t = l & 3;
        int n = 8 * j + g;
        int k = 16 * s + 2 * t;
        float f0 = B1[(size_t)k * 64 + n];
        float f1 = B1[(size_t)(k + 1) * 64 + n];
        float f2 = B1[(size_t)(k + 8) * 64 + n];
        float f3 = B1[(size_t)(k + 9) * 64 + n];
        g_bfrag[e] = make_uint4(pkbf(f0, f1), pkbf(f2, f3),
                                pkbf(bfres(f0), bfres(f1)), pkbf(bfres(f2), bfres(f3)));
    } else if (e < 8192 + 4096) {
        int e2 = e - 8192;
        int l = e2 & 31, j = (e2 >> 5) & 31, s = e2 >> 10;
        int g = l >> 2, t = l & 3;
        int n = 8 * j + g;
        int k = 16 * s + 2 * t;
        float f0 = B2[(size_t)k * D2 + n];
        float f1 = B2[(size_t)(k + 1) * D2 + n];
        float f2 = B2[(size_t)(k + 8) * D2 + n];
        float f3 = B2[(size_t)(k + 9) * D2 + n];
        g_bfrag2[e2] = make_uint4(pkbf(f0, f1), pkbf(f2, f3),
                                  pkbf(bfres(f0), bfres(f1)), pkbf(bfres(f2), bfres(f3)));
    }
}

// ---------------- GEMM1 via mma.sync bf16 split-3; writes UNSCALED bf16x2 ----------------
#define G1A_STRIDE 36
#define G1_SMEM_BYTES (2 * 256 * 72 * 2)
__global__ __launch_bounds__(256) void k_gemm1_mma(const float* __restrict__ A,
                                                   uint32_t* __restrict__ C) {
    extern __shared__ char smem[];
    uint32_t* Ah = (uint32_t*)smem;
    uint32_t* Al = (uint32_t*)(smem + 256 * 72 * 2);
    int tid  = threadIdx.x;
    int lane = tid & 31;
    int w    = tid >> 5;
    int g    = lane >> 2;
    int t    = lane & 3;
    int bm   = blockIdx.x * 256;

    float acc[2][8][4];
#pragma unroll
    for (int m = 0; m < 2; m++)
#pragma unroll
        for (int j = 0; j < 8; j++)
#pragma unroll
            for (int q = 0; q < 4; q++) acc[m][j][q] = 0.f;

    int lr = tid >> 4;
    int c4 = (tid & 15) * 4;

    for (int ch = 0; ch < 8; ch++) {
        int k0 = ch * 64;
#pragma unroll
        for (int i = 0; i < 16; i++) {
            int row  = lr + 16 * i;
            int grow = bm + row;
            float4 v = (grow < NN) ? *(const float4*)(A + (size_t)grow * FIN + k0 + c4)
                                   : make_float4(0.f, 0.f, 0.f, 0.f);
            int idx = row * G1A_STRIDE + (c4 >> 1);
            *(uint2*)&Ah[idx] = make_uint2(pkbf(v.x, v.y), pkbf(v.z, v.w));
            *(uint2*)&Al[idx] = make_uint2(pkbf(bfres(v.x), bfres(v.y)), pkbf(bfres(v.z), bfres(v.w)));
        }
        __syncthreads();
#pragma unroll
        for (int s4 = 0; s4 < 4; s4++) {
            int kk = s4 * 16;
            int gs = ch * 4 + s4;
            uint32_t ah[2][4], al[2][4];
#pragma unroll
            for (int m = 0; m < 2; m++) {
                int r0 = w * 32 + m * 16 + g;
                int kc = (kk + 2 * t) >> 1;
                ah[m][0] = Ah[r0 * G1A_STRIDE + kc];
                ah[m][1] = Ah[(r0 + 8) * G1A_STRIDE + kc];
                ah[m][2] = Ah[r0 * G1A_STRIDE + kc + 4];
                ah[m][3] = Ah[(r0 + 8) * G1A_STRIDE + kc + 4];
                al[m][0] = Al[r0 * G1A_STRIDE + kc];
                al[m][1] = Al[(r0 + 8) * G1A_STRIDE + kc];
                al[m][2] = Al[r0 * G1A_STRIDE + kc + 4];
                al[m][3] = Al[(r0 + 8) * G1A_STRIDE + kc + 4];
            }
#pragma unroll
            for (int j = 0; j < 8; j++) {
                uint4 bf4 = __ldg(&g_bfrag[(gs * 8 + j) * 32 + lane]);
#pragma unroll
                for (int m = 0; m < 2; m++) {
                    mma_bf16(acc[m][j], ah[m], bf4.x, bf4.y);
                    mma_bf16(acc[m][j], ah[m], bf4.z, bf4.w);
                    mma_bf16(acc[m][j], al[m], bf4.x, bf4.y);
                }
            }
        }
        __syncthreads();
    }
#pragma unroll
    for (int m = 0; m < 2; m++) {
        int row = bm + w * 32 + m * 16 + g;
#pragma unroll
        for (int j = 0; j < 8; j++) {
            int cp = 4 * j + t;
            if (row < NN)
                C[(size_t)row * 32 + cp] = pkbf(acc[m][j][0], acc[m][j][1]);
            if (row + 8 < NN)
                C[(size_t)(row + 8) * 32 + cp] = pkbf(acc[m][j][2], acc[m][j][3]);
        }
    }
}

// ---------------- scale xw1 by dinv (in place, bf16) ----------------
__global__ void k_scale_xw1(uint32_t* __restrict__ xw1) {
    int i = blockIdx.x * blockDim.x + threadIdx.x;   // over NN*32 uint32s
    if (i >= NN * 32) return;
    float dd = g_dinv[i >> 5];
    float2 v = upbf(xw1[i]);
    xw1[i] = pkbf(v.x * dd, v.y * dd);
}

// ---------------- gather 1: bf16 in -> bf16 out (relu+bias, dinv^2 scaling), unroll 8 ----
__global__ __launch_bounds__(256) void k_gather_bf2bf(const uint32_t* __restrict__ in,
                                                      uint32_t* __restrict__ out,
                                                      const float* __restrict__ bias) {
    int node = (blockIdx.x * blockDim.x + threadIdx.x) >> 5;
    if (node >= NN) return;
    int lane = threadIdx.x & 31;
    float dd = g_dinv[node];
    float2 self = upbf(in[node * 32 + lane]);
    float ax = self.x, ay = self.y;
    int e   = g_rowstart[node];
    int end = g_rowstart[node + 1];
    for (; e + 7 < end; e += 8) {
        int s[8];
#pragma unroll
        for (int q = 0; q < 8; q++) s[q] = __ldg(&g_csrsrc[e + q]);
        float2 v[8];
#pragma unroll
        for (int q = 0; q < 8; q++) v[q] = upbf(__ldg(&in[s[q] * 32 + lane]));
#pragma unroll
        for (int q = 0; q < 8; q++) { ax += v[q].x; ay += v[q].y; }
    }
    for (; e + 3 < end; e += 4) {
        int s[4];
#pragma unroll
        for (int q = 0; q < 4; q++) s[q] = __ldg(&g_csrsrc[e + q]);
        float2 v[4];
#pragma unroll
        for (int q = 0; q < 4; q++) v[q] = upbf(__ldg(&in[s[q] * 32 + lane]));
#pragma unroll
        for (int q = 0; q < 4; q++) { ax += v[q].x; ay += v[q].y; }
    }
    for (; e < end; e++) {
        float2 v = upbf(__ldg(&in[__ldg(&g_csrsrc[e]) * 32 + lane]));
        ax += v.x;
        ay += v.y;
    }
    float2 bb = ((const float2*)bias)[lane];
    ax = fmaxf(ax * dd + bb.x, 0.f) * dd;
    ay = fmaxf(ay * dd + bb.y, 0.f) * dd;
    out[node * 32 + lane] = pkbf(ax, ay);
}

// ---------------- gather 2: bf16 in -> fp32 out (plain aggregate, dinv scale), unroll 8 ----
__global__ __launch_bounds__(256) void k_gather_bf2f(const uint32_t* __restrict__ in,
                                                     float* __restrict__ out) {
    int node = (blockIdx.x * blockDim.x + threadIdx.x) >> 5;
    if (node >= NN) return;
    int lane = threadIdx.x & 31;
    float dd = g_dinv[node];
    float2 self = upbf(in[node * 32 + lane]);
    float ax = self.x, ay = self.y;
    int e   = g_rowstart[node];
    int end = g_rowstart[node + 1];
    for (; e + 7 < end; e += 8) {
        int s[8];
#pragma unroll
        for (int q = 0; q < 8; q++) s[q] = __ldg(&g_csrsrc[e + q]);
        float2 v[8];
#pragma unroll
        for (int q = 0; q < 8; q++) v[q] = upbf(__ldg(&in[s[q] * 32 + lane]));
#pragma unroll
        for (int q = 0; q < 8; q++) { ax += v[q].x; ay += v[q].y; }
    }
    for (; e + 3 < end; e += 4) {
        int s[4];
#pragma unroll
        for (int q = 0; q < 4; q++) s[q] = __ldg(&g_csrsrc[e + q]);
        float2 v[4];
#pragma unroll
        for (int q = 0; q < 4; q++) v[q] = upbf(__ldg(&in[s[q] * 32 + lane]));
#pragma unroll
        for (int q = 0; q < 4; q++) { ax += v[q].x; ay += v[q].y; }
    }
    for (; e < end; e++) {
        float2 v = upbf(__ldg(&in[__ldg(&g_csrsrc[e]) * 32 + lane]));
        ax += v.x;
        ay += v.y;
    }
    ((float2*)(out + (size_t)node * 64))[lane] = make_float2(ax * dd, ay * dd);
}

// ---------------- GEMM2: one block per 256 rows, loops all 4 n-chunks; writes scaled z0 ----
__global__ __launch_bounds__(256) void k_gemm2_mma(const float* __restrict__ A,
                                                   const float* __restrict__ bias,
                                                   const float* __restrict__ W3) {
    extern __shared__ char smem[];
    uint32_t* Ah = (uint32_t*)smem;
    uint32_t* Al = (uint32_t*)(smem + 256 * 72 * 2);
    __shared__ float zpart[256];
    int tid  = threadIdx.x;
    int lane = tid & 31;
    int w    = tid >> 5;
    int g    = lane >> 2;
    int t    = lane & 3;
    int bm   = blockIdx.x * 256;
    zpart[tid] = 0.f;

    int lr = tid >> 4;
    int c4 = (tid & 15) * 4;
#pragma unroll
    for (int i = 0; i < 16; i++) {
        int row  = lr + 16 * i;
        int grow = bm + row;
        float4 v = (grow < NN) ? *(const float4*)(A + (size_t)grow * D1 + c4)
                               : make_float4(0.f, 0.f, 0.f, 0.f);
        int idx = row * G1A_STRIDE + (c4 >> 1);
        *(uint2*)&Ah[idx] = make_uint2(pkbf(v.x, v.y), pkbf(v.z, v.w));
        *(uint2*)&Al[idx] = make_uint2(pkbf(bfres(v.x), bfres(v.y)), pkbf(bfres(v.z), bfres(v.w)));
    }
    __syncthreads();

    for (int c = 0; c < 4; c++) {
        float acc[2][8][4];
#pragma unroll
        for (int m = 0; m < 2; m++)
#pragma unroll
            for (int j = 0; j < 8; j++)
#pragma unroll
                for (int q = 0; q < 4; q++) acc[m][j][q] = 0.f;
#pragma unroll
        for (int s4 = 0; s4 < 4; s4++) {
            int kk = s4 * 16;
            uint32_t ah[2][4], al[2][4];
#pragma unroll
            for (int m = 0; m < 2; m++) {
                int r0 = w * 32 + m * 16 + g;
                int kc = (kk + 2 * t) >> 1;
                ah[m][0] = Ah[r0 * G1A_STRIDE + kc];
                ah[m][1] = Ah[(r0 + 8) * G1A_STRIDE + kc];
                ah[m][2] = Ah[r0 * G1A_STRIDE + kc + 4];
                ah[m][3] = Ah[(r0 + 8) * G1A_STRIDE + kc + 4];
                al[m][0] = Al[r0 * G1A_STRIDE + kc];
                al[m][1] = Al[(r0 + 8) * G1A_STRIDE + kc];
                al[m][2] = Al[r0 * G1A_STRIDE + kc + 4];
                al[m][3] = Al[(r0 + 8) * G1A_STRIDE + kc + 4];
            }
#pragma unroll
            for (int j = 0; j < 8; j++) {
                uint4 bf4 = __ldg(&g_bfrag2[(s4 * 32 + c * 8 + j) * 32 + lane]);
#pragma unroll
                for (int m = 0; m < 2; m++) {
                    mma_bf16(acc[m][j], ah[m], bf4.x, bf4.y);
                    mma_bf16(acc[m][j], ah[m], bf4.z, bf4.w);
                    mma_bf16(acc[m][j], al[m], bf4.x, bf4.y);
                }
            }
        }
#pragma unroll
        for (int m = 0; m < 2; m++) {
            int rl0 = w * 32 + m * 16 + g;
            float s0 = 0.f, s1 = 0.f;
#pragma unroll
            for (int j = 0; j < 8; j++) {
                int col = c * 64 + 8 * j + 2 * t;
                float b0 = bias[col], b1 = bias[col + 1];
                float w0 = W3[col],  w1 = W3[col + 1];
                s0 += fmaxf(acc[m][j][0] + b0, 0.f) * w0 + fmaxf(acc[m][j][1] + b1, 0.f) * w1;
                s1 += fmaxf(acc[m][j][2] + b0, 0.f) * w0 + fmaxf(acc[m][j][3] + b1, 0.f) * w1;
            }
            atomicAdd(&zpart[rl0],     s0);
            atomicAdd(&zpart[rl0 + 8], s1);
        }
    }
    __syncthreads();
    int row = bm + tid;
    if (row < NN) g_z0[row] = zpart[tid] * g_dinv[row];
}

// ---------------- fused z aggregation + BCE loss (z0 pre-scaled) ----------------
__global__ void k_zero(float* out) {
    if (blockIdx.x == 0 && threadIdx.x == 0) out[0] = 0.f;
}
__global__ __launch_bounds__(256) void k_zagg_loss(const float* __restrict__ b3,
                                                   const float* __restrict__ y,
                                                   float* __restrict__ out) {
    __shared__ float red[256];
    int i = blockIdx.x * blockDim.x + threadIdx.x;
    float v = 0.f;
    if (i < NN) {
        float dd  = g_dinv[i];
        float acc = g_z0[i];
        int e = g_rowstart[i], end = g_rowstart[i + 1];
        for (; e + 7 < end; e += 8) {
            int s[8];
#pragma unroll
            for (int q = 0; q < 8; q++) s[q] = __ldg(&g_csrsrc[e + q]);
            float vv = 0.f;
#pragma unroll
            for (int q = 0; q < 8; q++) vv += __ldg(&g_z0[s[q]]);
            acc += vv;
        }
        for (; e < end; e++) acc += __ldg(&g_z0[__ldg(&g_csrsrc[e])]);
        float z = acc * dd + b3[0];
        float t = y[i];
        v = fmaxf(z, 0.f) - z * t + log1pf(expf(-fabsf(z)));
    }
    red[threadIdx.x] = v;
    __syncthreads();
    for (int s = 128; s > 0; s >>= 1) {
        if (threadIdx.x < s) red[threadIdx.x] += red[threadIdx.x + s];
        __syncthreads();
    }
    if (threadIdx.x == 0) atomicAdd(out, red[0] * (1.0f / NN));
}

// ---------------- launcher ----------------
static cudaStream_t g_s2 = 0;
static cudaEvent_t  g_evFork = 0, g_evJoin = 0;

extern "C" void kernel_launch(void* const* d_in, const int* in_sizes, int n_in,
                              void* d_out, int out_size) {
    const float* x  = (const float*)d_in[0];
    const int*   ei = (const int*)  d_in[1];
    const float* y  = (const float*)d_in[2];
    const float* W1 = (const float*)d_in[3];
    const float* b1 = (const float*)d_in[4];
    const float* W2 = (const float*)d_in[5];
    const float* b2 = (const float*)d_in[6];
    const float* W3 = (const float*)d_in[7];
    const float* b3 = (const float*)d_in[8];
    const int* src = ei;
    const int* dst = ei + NE;
    float* out = (float*)d_out;

    uint32_t *p_xw1, *p_h1;
    float *p_ah1;
    cudaGetSymbolAddress((void**)&p_xw1, g_xw1);
    cudaGetSymbolAddress((void**)&p_h1,  g_h1);
    cudaGetSymbolAddress((void**)&p_ah1, g_ah1);

    cudaFuncSetAttribute(k_gemm1_mma, cudaFuncAttributeMaxDynamicSharedMemorySize, G1_SMEM_BYTES);
    cudaFuncSetAttribute(k_gemm2_mma, cudaFuncAttributeMaxDynamicSharedMemorySize, G1_SMEM_BYTES);

    if (!g_s2) {
        cudaStreamCreateWithFlags(&g_s2, cudaStreamNonBlocking);
        cudaEventCreateWithFlags(&g_evFork, cudaEventDisableTiming);
        cudaEventCreateWithFlags(&g_evJoin, cudaEventDisableTiming);
    }

    const int T = 256;
    // ---- fork at t=0: full CSR build on s2  ||  packW + gemm1 (unscaled) on default ----
    k_zero <<<1, 32>>>(out);
    cudaEventRecord(g_evFork, 0);
    cudaStreamWaitEvent(g_s2, g_evFork, 0);
    k_clear<<<(NN + T - 1) / T, T, 0, g_s2>>>();
    k_hist <<<(NE + T - 1) / T, T, 0, g_s2>>>(dst);
    k_dinv <<<(NN + T - 1) / T, T, 0, g_s2>>>();
    k_scan1<<<SCAN_NB, SCAN_B, 0, g_s2>>>();
    k_scan2<<<1, 128, 0, g_s2>>>();
    k_scan3<<<(NN + T - 1) / T, T, 0, g_s2>>>();
    k_fill <<<(NE + T - 1) / T, T, 0, g_s2>>>(src, dst);
    cudaEventRecord(g_evJoin, g_s2);

    k_packW<<<48, 256>>>(W1, W2);
    k_gemm1_mma<<<(NN + 255) / 256, 256, G1_SMEM_BYTES>>>(x, p_xw1);

    // ---- join, then apply dinv scaling to xw1 ----
    cudaStreamWaitEvent(0, g_evJoin, 0);
    k_scale_xw1<<<(NN * 32 + T - 1) / T, T>>>(p_xw1);

    // ---- layer 1 aggregate ----
    k_gather_bf2bf<<<(NN * 32 + T - 1) / T, T>>>(p_xw1, p_h1, b1);

    // ---- layer 2 + fused layer-3 matvec ----
    k_gather_bf2f<<<(NN * 32 + T - 1) / T, T>>>(p_h1, p_ah1);
    k_gemm2_mma<<<(NN + 255) / 256, 256, G1_SMEM_BYTES>>>(p_ah1, b2, W3);

    // ---- z aggregation + loss ----
    k_zagg_loss<<<(NN + T - 1) / T, T>>>(b3, y, out);
}

// round 14
// speedup vs baseline: 1.4775x; 1.0484x over previous
#include <cuda_runtime.h>
#include <cuda_bf16.h>
#include <stdint.h>
#include <math.h>

#define NN 100000
#define NE 1600000
#define FIN 512
#define D1 64
#define D2 256
#define SCAN_B 1024
#define SCAN_NB ((NN + SCAN_B - 1) / SCAN_B)

__device__ float    g_dinv[NN];
__device__ int      g_cnt[NN];
__device__ int      g_tmp[NN];
__device__ int      g_bsum[SCAN_NB];
__device__ int      g_rowstart[NN + 1];
__device__ int      g_csrsrc[NE];
__device__ uint4    g_bfrag[8192];             // packed W1 b-frags
__device__ uint4    g_bfrag2[4096];            // packed W2 b-frags
__device__ uint32_t g_xw1[(size_t)NN * 32];    // bf16x2 x@W1 (unscaled, then dinv-scaled in place)
__device__ uint32_t g_h1 [(size_t)NN * 32];    // bf16x2, dinv-scaled relu(A xw1 + b1)
__device__ float    g_ah1[(size_t)NN * D1];    // A h1 (fp32)
__device__ float    g_z0 [NN];                 // dinv-scaled h2@W3

// ---------------- bf16 helpers ----------------
__device__ __forceinline__ uint32_t pkbf(float a, float b) {
    __nv_bfloat162 h = __floats2bfloat162_rn(a, b);
    return *(uint32_t*)&h;
}
__device__ __forceinline__ float2 upbf(uint32_t v) {
    __nv_bfloat162 h = *(__nv_bfloat162*)&v;
    return __bfloat1622float2(h);
}
// split (a,b) into bf16 hi pack + bf16 lo (residual) pack — extracts hi parts by bit ops
__device__ __forceinline__ void split2(float a, float b, uint32_t& hi, uint32_t& lo) {
    hi = pkbf(a, b);
    float ha = __uint_as_float(hi << 16);
    float hb = __uint_as_float(hi & 0xffff0000u);
    lo = pkbf(a - ha, b - hb);
}
__device__ __forceinline__ void mma_bf16(float* c, const uint32_t* a, uint32_t b0, uint32_t b1) {
    asm("mma.sync.aligned.m16n8k16.row.col.f32.bf16.bf16.f32 "
        "{%0,%1,%2,%3}, {%4,%5,%6,%7}, {%8,%9}, {%0,%1,%2,%3};"
        : "+f"(c[0]), "+f"(c[1]), "+f"(c[2]), "+f"(c[3])
        : "r"(a[0]), "r"(a[1]), "r"(a[2]), "r"(a[3]), "r"(b0), "r"(b1));
}

// ---------------- CSR build ----------------
__global__ void k_clear() {
    int i = blockIdx.x * blockDim.x + threadIdx.x;
    if (i < NN) g_cnt[i] = 0;
}
__global__ void k_hist(const int* __restrict__ dst) {
    int e = blockIdx.x * blockDim.x + threadIdx.x;
    if (e < NE) atomicAdd(&g_cnt[dst[e]], 1);
}
__global__ void k_dinv() {
    int i = blockIdx.x * blockDim.x + threadIdx.x;
    if (i < NN) g_dinv[i] = rsqrtf((float)g_cnt[i] + 1.0f);
}
__global__ __launch_bounds__(SCAN_B) void k_scan1() {
    __shared__ int sh[SCAN_B];
    int t = threadIdx.x;
    int i = blockIdx.x * SCAN_B + t;
    sh[t] = (i < NN) ? g_cnt[i] : 0;
    __syncthreads();
#pragma unroll
    for (int off = 1; off < SCAN_B; off <<= 1) {
        int v = (t >= off) ? sh[t - off] : 0;
        __syncthreads();
        sh[t] += v;
        __syncthreads();
    }
    if (i < NN) g_tmp[i] = sh[t];
    if (t == SCAN_B - 1) g_bsum[blockIdx.x] = sh[t];
}
__global__ __launch_bounds__(128) void k_scan2() {
    __shared__ int sh[128];
    int t = threadIdx.x;
    int v0 = (t < SCAN_NB) ? g_bsum[t] : 0;
    sh[t] = v0;
    __syncthreads();
#pragma unroll
    for (int off = 1; off < 128; off <<= 1) {
        int v = (t >= off) ? sh[t - off] : 0;
        __syncthreads();
        sh[t] += v;
        __syncthreads();
    }
    if (t < SCAN_NB) g_bsum[t] = sh[t] - v0;
}
__global__ void k_scan3() {
    int i = blockIdx.x * blockDim.x + threadIdx.x;
    if (i < NN) {
        g_rowstart[i + 1] = g_tmp[i] + g_bsum[i >> 10];
        if (i == 0) g_rowstart[0] = 0;
        g_cnt[i] = 0;
    }
}
__global__ void k_fill(const int* __restrict__ src, const int* __restrict__ dst) {
    int e = blockIdx.x * blockDim.x + threadIdx.x;
    if (e < NE) {
        int d = dst[e];
        int pos = g_rowstart[d] + atomicAdd(&g_cnt[d], 1);
        g_csrsrc[pos] = src[e];
    }
}

// ---------------- pack W1 [512,64] + W2 [64,256] into mma b-fragments ----------------
__global__ void k_packW(const float* __restrict__ B1, const float* __restrict__ B2) {
    int e = blockIdx.x * blockDim.x + threadIdx.x;
    if (e < 8192) {
        int l = e & 31, j = (e >> 5) & 7, s = e >> 8;
        int g = l >> 2, t = l & 3;
        int n = 8 * j + g;
        int k = 16 * s + 2 * t;
        float f0 = B1[(size_t)k * 64 + n];
        float f1 = B1[(size_t)(k + 1) * 64 + n];
        float f2 = B1[(size_t)(k + 8) * 64 + n];
        float f3 = B1[(size_t)(k + 9) * 64 + n];
        uint32_t h01, l01, h23, l23;
        split2(f0, f1, h01, l01);
        split2(f2, f3, h23, l23);
        g_bfrag[e] = make_uint4(h01, h23, l01, l23);
    } else if (e < 8192 + 4096) {
        int e2 = e - 8192;
        int l = e2 & 31, j = (e2 >> 5) & 31, s = e2 >> 10;
        int g = l >> 2, t = l & 3;
        int n = 8 * j + g;
        int k = 16 * s + 2 * t;
        float f0 = B2[(size_t)k * D2 + n];
        float f1 = B2[(size_t)(k + 1) * D2 + n];
        float f2 = B2[(size_t)(k + 8) * D2 + n];
        float f3 = B2[(size_t)(k + 9) * D2 + n];
        uint32_t h01, l01, h23, l23;
        split2(f0, f1, h01, l01);
        split2(f2, f3, h23, l23);
        g_bfrag2[e2] = make_uint4(h01, h23, l01, l23);
    }
}

// ---------------- GEMM1 via mma.sync bf16 split-3; writes UNSCALED bf16x2 ----------------
#define G1A_STRIDE 36
#define G1_SMEM_BYTES (2 * 256 * 72 * 2)
__global__ __launch_bounds__(256) void k_gemm1_mma(const float* __restrict__ A,
                                                   uint32_t* __restrict__ C) {
    extern __shared__ char smem[];
    uint32_t* Ah = (uint32_t*)smem;
    uint32_t* Al = (uint32_t*)(smem + 256 * 72 * 2);
    int tid  = threadIdx.x;
    int lane = tid & 31;
    int w    = tid >> 5;
    int g    = lane >> 2;
    int t    = lane & 3;
    int bm   = blockIdx.x * 256;

    float acc[2][8][4];
#pragma unroll
    for (int m = 0; m < 2; m++)
#pragma unroll
        for (int j = 0; j < 8; j++)
#pragma unroll
            for (int q = 0; q < 4; q++) acc[m][j][q] = 0.f;

    int lr = tid >> 4;
    int c4 = (tid & 15) * 4;

    for (int ch = 0; ch < 8; ch++) {
        int k0 = ch * 64;
#pragma unroll
        for (int i = 0; i < 16; i++) {
            int row  = lr + 16 * i;
            int grow = bm + row;
            float4 v = (grow < NN) ? *(const float4*)(A + (size_t)grow * FIN + k0 + c4)
                                   : make_float4(0.f, 0.f, 0.f, 0.f);
            uint32_t h01, l01, h23, l23;
            split2(v.x, v.y, h01, l01);
            split2(v.z, v.w, h23, l23);
            int idx = row * G1A_STRIDE + (c4 >> 1);
            *(uint2*)&Ah[idx] = make_uint2(h01, h23);
            *(uint2*)&Al[idx] = make_uint2(l01, l23);
        }
        __syncthreads();
#pragma unroll
        for (int s4 = 0; s4 < 4; s4++) {
            int kk = s4 * 16;
            int gs = ch * 4 + s4;
            uint32_t ah[2][4], al[2][4];
#pragma unroll
            for (int m = 0; m < 2; m++) {
                int r0 = w * 32 + m * 16 + g;
                int kc = (kk + 2 * t) >> 1;
                ah[m][0] = Ah[r0 * G1A_STRIDE + kc];
                ah[m][1] = Ah[(r0 + 8) * G1A_STRIDE + kc];
                ah[m][2] = Ah[r0 * G1A_STRIDE + kc + 4];
                ah[m][3] = Ah[(r0 + 8) * G1A_STRIDE + kc + 4];
                al[m][0] = Al[r0 * G1A_STRIDE + kc];
                al[m][1] = Al[(r0 + 8) * G1A_STRIDE + kc];
                al[m][2] = Al[r0 * G1A_STRIDE + kc + 4];
                al[m][3] = Al[(r0 + 8) * G1A_STRIDE + kc + 4];
            }
#pragma unroll
            for (int j = 0; j < 8; j++) {
                uint4 bf4 = __ldg(&g_bfrag[(gs * 8 + j) * 32 + lane]);
#pragma unroll
                for (int m = 0; m < 2; m++) {
                    mma_bf16(acc[m][j], ah[m], bf4.x, bf4.y);
                    mma_bf16(acc[m][j], ah[m], bf4.z, bf4.w);
                    mma_bf16(acc[m][j], al[m], bf4.x, bf4.y);
                }
            }
        }
        __syncthreads();
    }
#pragma unroll
    for (int m = 0; m < 2; m++) {
        int row = bm + w * 32 + m * 16 + g;
#pragma unroll
        for (int j = 0; j < 8; j++) {
            int cp = 4 * j + t;
            if (row < NN)
                C[(size_t)row * 32 + cp] = pkbf(acc[m][j][0], acc[m][j][1]);
            if (row + 8 < NN)
                C[(size_t)(row + 8) * 32 + cp] = pkbf(acc[m][j][2], acc[m][j][3]);
        }
    }
}

// ---------------- scale xw1 by dinv (in place, bf16) ----------------
__global__ void k_scale_xw1(uint32_t* __restrict__ xw1) {
    int i = blockIdx.x * blockDim.x + threadIdx.x;   // over NN*32 uint32s
    if (i >= NN * 32) return;
    float dd = g_dinv[i >> 5];
    float2 v = upbf(xw1[i]);
    xw1[i] = pkbf(v.x * dd, v.y * dd);
}

// ---------------- gather 1: bf16 in -> bf16 out (relu+bias, dinv^2 scaling), unroll 8 ----
__global__ __launch_bounds__(256) void k_gather_bf2bf(const uint32_t* __restrict__ in,
                                                      uint32_t* __restrict__ out,
                                                      const float* __restrict__ bias) {
    int node = (blockIdx.x * blockDim.x + threadIdx.x) >> 5;
    if (node >= NN) return;
    int lane = threadIdx.x & 31;
    float dd = g_dinv[node];
    float2 self = upbf(in[node * 32 + lane]);
    float ax = self.x, ay = self.y;
    int e   = g_rowstart[node];
    int end = g_rowstart[node + 1];
    for (; e + 7 < end; e += 8) {
        int s[8];
#pragma unroll
        for (int q = 0; q < 8; q++) s[q] = __ldg(&g_csrsrc[e + q]);
        float2 v[8];
#pragma unroll
        for (int q = 0; q < 8; q++) v[q] = upbf(__ldg(&in[s[q] * 32 + lane]));
#pragma unroll
        for (int q = 0; q < 8; q++) { ax += v[q].x; ay += v[q].y; }
    }
    for (; e + 3 < end; e += 4) {
        int s[4];
#pragma unroll
        for (int q = 0; q < 4; q++) s[q] = __ldg(&g_csrsrc[e + q]);
        float2 v[4];
#pragma unroll
        for (int q = 0; q < 4; q++) v[q] = upbf(__ldg(&in[s[q] * 32 + lane]));
#pragma unroll
        for (int q = 0; q < 4; q++) { ax += v[q].x; ay += v[q].y; }
    }
    for (; e < end; e++) {
        float2 v = upbf(__ldg(&in[__ldg(&g_csrsrc[e]) * 32 + lane]));
        ax += v.x;
        ay += v.y;
    }
    float2 bb = ((const float2*)bias)[lane];
    ax = fmaxf(ax * dd + bb.x, 0.f) * dd;
    ay = fmaxf(ay * dd + bb.y, 0.f) * dd;
    out[node * 32 + lane] = pkbf(ax, ay);
}

// ---------------- gather 2: bf16 in -> fp32 out (plain aggregate, dinv scale), unroll 8 ----
__global__ __launch_bounds__(256) void k_gather_bf2f(const uint32_t* __restrict__ in,
                                                     float* __restrict__ out) {
    int node = (blockIdx.x * blockDim.x + threadIdx.x) >> 5;
    if (node >= NN) return;
    int lane = threadIdx.x & 31;
    float dd = g_dinv[node];
    float2 self = upbf(in[node * 32 + lane]);
    float ax = self.x, ay = self.y;
    int e   = g_rowstart[node];
    int end = g_rowstart[node + 1];
    for (; e + 7 < end; e += 8) {
        int s[8];
#pragma unroll
        for (int q = 0; q < 8; q++) s[q] = __ldg(&g_csrsrc[e + q]);
        float2 v[8];
#pragma unroll
        for (int q = 0; q < 8; q++) v[q] = upbf(__ldg(&in[s[q] * 32 + lane]));
#pragma unroll
        for (int q = 0; q < 8; q++) { ax += v[q].x; ay += v[q].y; }
    }
    for (; e + 3 < end; e += 4) {
        int s[4];
#pragma unroll
        for (int q = 0; q < 4; q++) s[q] = __ldg(&g_csrsrc[e + q]);
        float2 v[4];
#pragma unroll
        for (int q = 0; q < 4; q++) v[q] = upbf(__ldg(&in[s[q] * 32 + lane]));
#pragma unroll
        for (int q = 0; q < 4; q++) { ax += v[q].x; ay += v[q].y; }
    }
    for (; e < end; e++) {
        float2 v = upbf(__ldg(&in[__ldg(&g_csrsrc[e]) * 32 + lane]));
        ax += v.x;
        ay += v.y;
    }
    ((float2*)(out + (size_t)node * 64))[lane] = make_float2(ax * dd, ay * dd);
}

// ---------------- GEMM2: one block per 256 rows, loops all 4 n-chunks; writes scaled z0 ----
__global__ __launch_bounds__(256) void k_gemm2_mma(const float* __restrict__ A,
                                                   const float* __restrict__ bias,
                                                   const float* __restrict__ W3) {
    extern __shared__ char smem[];
    uint32_t* Ah = (uint32_t*)smem;
    uint32_t* Al = (uint32_t*)(smem + 256 * 72 * 2);
    __shared__ float zpart[256];
    int tid  = threadIdx.x;
    int lane = tid & 31;
    int w    = tid >> 5;
    int g    = lane >> 2;
    int t    = lane & 3;
    int bm   = blockIdx.x * 256;
    zpart[tid] = 0.f;

    int lr = tid >> 4;
    int c4 = (tid & 15) * 4;
#pragma unroll
    for (int i = 0; i < 16; i++) {
        int row  = lr + 16 * i;
        int grow = bm + row;
        float4 v = (grow < NN) ? *(const float4*)(A + (size_t)grow * D1 + c4)
                               : make_float4(0.f, 0.f, 0.f, 0.f);
        uint32_t h01, l01, h23, l23;
        split2(v.x, v.y, h01, l01);
        split2(v.z, v.w, h23, l23);
        int idx = row * G1A_STRIDE + (c4 >> 1);
        *(uint2*)&Ah[idx] = make_uint2(h01, h23);
        *(uint2*)&Al[idx] = make_uint2(l01, l23);
    }
    __syncthreads();

    for (int c = 0; c < 4; c++) {
        float acc[2][8][4];
#pragma unroll
        for (int m = 0; m < 2; m++)
#pragma unroll
            for (int j = 0; j < 8; j++)
#pragma unroll
                for (int q = 0; q < 4; q++) acc[m][j][q] = 0.f;
#pragma unroll
        for (int s4 = 0; s4 < 4; s4++) {
            int kk = s4 * 16;
            uint32_t ah[2][4], al[2][4];
#pragma unroll
            for (int m = 0; m < 2; m++) {
                int r0 = w * 32 + m * 16 + g;
                int kc = (kk + 2 * t) >> 1;
                ah[m][0] = Ah[r0 * G1A_STRIDE + kc];
                ah[m][1] = Ah[(r0 + 8) * G1A_STRIDE + kc];
                ah[m][2] = Ah[r0 * G1A_STRIDE + kc + 4];
                ah[m][3] = Ah[(r0 + 8) * G1A_STRIDE + kc + 4];
                al[m][0] = Al[r0 * G1A_STRIDE + kc];
                al[m][1] = Al[(r0 + 8) * G1A_STRIDE + kc];
                al[m][2] = Al[r0 * G1A_STRIDE + kc + 4];
                al[m][3] = Al[(r0 + 8) * G1A_STRIDE + kc + 4];
            }
#pragma unroll
            for (int j = 0; j < 8; j++) {
                uint4 bf4 = __ldg(&g_bfrag2[(s4 * 32 + c * 8 + j) * 32 + lane]);
#pragma unroll
                for (int m = 0; m < 2; m++) {
                    mma_bf16(acc[m][j], ah[m], bf4.x, bf4.y);
                    mma_bf16(acc[m][j], ah[m], bf4.z, bf4.w);
                    mma_bf16(acc[m][j], al[m], bf4.x, bf4.y);
                }
            }
        }
#pragma unroll
        for (int m = 0; m < 2; m++) {
            int rl0 = w * 32 + m * 16 + g;
            float s0 = 0.f, s1 = 0.f;
#pragma unroll
            for (int j = 0; j < 8; j++) {
                int col = c * 64 + 8 * j + 2 * t;
                float b0 = bias[col], b1 = bias[col + 1];
                float w0 = W3[col],  w1 = W3[col + 1];
                s0 += fmaxf(acc[m][j][0] + b0, 0.f) * w0 + fmaxf(acc[m][j][1] + b1, 0.f) * w1;
                s1 += fmaxf(acc[m][j][2] + b0, 0.f) * w0 + fmaxf(acc[m][j][3] + b1, 0.f) * w1;
            }
            atomicAdd(&zpart[rl0],     s0);
            atomicAdd(&zpart[rl0 + 8], s1);
        }
    }
    __syncthreads();
    int row = bm + tid;
    if (row < NN) g_z0[row] = zpart[tid] * g_dinv[row];
}

// ---------------- fused z aggregation + BCE loss (z0 pre-scaled) ----------------
__global__ void k_zero(float* out) {
    if (blockIdx.x == 0 && threadIdx.x == 0) out[0] = 0.f;
}
__global__ __launch_bounds__(256) void k_zagg_loss(const float* __restrict__ b3,
                                                   const float* __restrict__ y,
                                                   float* __restrict__ out) {
    __shared__ float red[256];
    int i = blockIdx.x * blockDim.x + threadIdx.x;
    float v = 0.f;
    if (i < NN) {
        float dd  = g_dinv[i];
        float acc = g_z0[i];
        int e = g_rowstart[i], end = g_rowstart[i + 1];
        for (; e + 7 < end; e += 8) {
            int s[8];
#pragma unroll
            for (int q = 0; q < 8; q++) s[q] = __ldg(&g_csrsrc[e + q]);
            float vv = 0.f;
#pragma unroll
            for (int q = 0; q < 8; q++) vv += __ldg(&g_z0[s[q]]);
            acc += vv;
        }
        for (; e < end; e++) acc += __ldg(&g_z0[__ldg(&g_csrsrc[e])]);
        float z = acc * dd + b3[0];
        float t = y[i];
        v = fmaxf(z, 0.f) - z * t + log1pf(expf(-fabsf(z)));
    }
    red[threadIdx.x] = v;
    __syncthreads();
    for (int s = 128; s > 0; s >>= 1) {
        if (threadIdx.x < s) red[threadIdx.x] += red[threadIdx.x + s];
        __syncthreads();
    }
    if (threadIdx.x == 0) atomicAdd(out, red[0] * (1.0f / NN));
}

// ---------------- launcher ----------------
static cudaStream_t g_s2 = 0;
static cudaEvent_t  g_evFork = 0, g_evJoin = 0, g_evDinv = 0;

extern "C" void kernel_launch(void* const* d_in, const int* in_sizes, int n_in,
                              void* d_out, int out_size) {
    const float* x  = (const float*)d_in[0];
    const int*   ei = (const int*)  d_in[1];
    const float* y  = (const float*)d_in[2];
    const float* W1 = (const float*)d_in[3];
    const float* b1 = (const float*)d_in[4];
    const float* W2 = (const float*)d_in[5];
    const float* b2 = (const float*)d_in[6];
    const float* W3 = (const float*)d_in[7];
    const float* b3 = (const float*)d_in[8];
    const int* src = ei;
    const int* dst = ei + NE;
    float* out = (float*)d_out;

    uint32_t *p_xw1, *p_h1;
    float *p_ah1;
    cudaGetSymbolAddress((void**)&p_xw1, g_xw1);
    cudaGetSymbolAddress((void**)&p_h1,  g_h1);
    cudaGetSymbolAddress((void**)&p_ah1, g_ah1);

    cudaFuncSetAttribute(k_gemm1_mma, cudaFuncAttributeMaxDynamicSharedMemorySize, G1_SMEM_BYTES);
    cudaFuncSetAttribute(k_gemm2_mma, cudaFuncAttributeMaxDynamicSharedMemorySize, G1_SMEM_BYTES);

    if (!g_s2) {
        cudaStreamCreateWithFlags(&g_s2, cudaStreamNonBlocking);
        cudaEventCreateWithFlags(&g_evFork, cudaEventDisableTiming);
        cudaEventCreateWithFlags(&g_evJoin, cudaEventDisableTiming);
        cudaEventCreateWithFlags(&g_evDinv, cudaEventDisableTiming);
    }

    const int T = 256;
    // ---- fork at t=0: full CSR build on s2  ||  packW + gemm1 (unscaled) on default ----
    k_zero <<<1, 32>>>(out);
    cudaEventRecord(g_evFork, 0);
    cudaStreamWaitEvent(g_s2, g_evFork, 0);
    k_clear<<<(NN + T - 1) / T, T, 0, g_s2>>>();
    k_hist <<<(NE + T - 1) / T, T, 0, g_s2>>>(dst);
    k_dinv <<<(NN + T - 1) / T, T, 0, g_s2>>>();
    cudaEventRecord(g_evDinv, g_s2);
    k_scan1<<<SCAN_NB, SCAN_B, 0, g_s2>>>();
    k_scan2<<<1, 128, 0, g_s2>>>();
    k_scan3<<<(NN + T - 1) / T, T, 0, g_s2>>>();
    k_fill <<<(NE + T - 1) / T, T, 0, g_s2>>>(src, dst);
    cudaEventRecord(g_evJoin, g_s2);

    k_packW<<<48, 256>>>(W1, W2);
    k_gemm1_mma<<<(NN + 255) / 256, 256, G1_SMEM_BYTES>>>(x, p_xw1);

    // ---- scale xw1 as soon as dinv is ready (overlaps with k_fill on s2) ----
    cudaStreamWaitEvent(0, g_evDinv, 0);
    k_scale_xw1<<<(NN * 32 + T - 1) / T, T>>>(p_xw1);

    // ---- join with CSR build, then layer-1 aggregate ----
    cudaStreamWaitEvent(0, g_evJoin, 0);
    k_gather_bf2bf<<<(NN * 32 + T - 1) / T, T>>>(p_xw1, p_h1, b1);

    // ---- layer 2 + fused layer-3 matvec ----
    k_gather_bf2f<<<(NN * 32 + T - 1) / T, T>>>(p_h1, p_ah1);
    k_gemm2_mma<<<(NN + 255) / 256, 256, G1_SMEM_BYTES>>>(p_ah1, b2, W3);

    // ---- z aggregation + loss ----
    k_zagg_loss<<<(NN + T - 1) / T, T>>>(b3, y, out);
}

// round 15
// speedup vs baseline: 1.4828x; 1.0035x over previous
#include <cuda_runtime.h>
#include <cuda_bf16.h>
#include <stdint.h>
#include <math.h>

#define NN 100000
#define NE 1600000
#define FIN 512
#define D1 64
#define D2 256
#define SCAN_B 1024
#define SCAN_NB ((NN + SCAN_B - 1) / SCAN_B)

__device__ float    g_dinv[NN];
__device__ int      g_cnt[NN];
__device__ int      g_tmp[NN];
__device__ int      g_bsum[SCAN_NB];
__device__ int      g_rowstart[NN + 1];
__device__ int      g_csrsrc[NE];
__device__ uint4    g_bfrag[8192];             // packed W1 b-frags
__device__ uint4    g_bfrag2[4096];            // packed W2 b-frags
__device__ uint32_t g_xw1[(size_t)NN * 32];    // bf16x2 x@W1 (unscaled, then dinv-scaled in place)
__device__ uint32_t g_h1 [(size_t)NN * 32];    // bf16x2, dinv-scaled relu(A xw1 + b1)
__device__ float    g_ah1[(size_t)NN * D1];    // A h1 (fp32)
__device__ float    g_z0 [NN];                 // dinv-scaled h2@W3

// ---------------- bf16 helpers ----------------
__device__ __forceinline__ uint32_t pkbf(float a, float b) {
    __nv_bfloat162 h = __floats2bfloat162_rn(a, b);
    return *(uint32_t*)&h;
}
__device__ __forceinline__ float2 upbf(uint32_t v) {
    __nv_bfloat162 h = *(__nv_bfloat162*)&v;
    return __bfloat1622float2(h);
}
// split (a,b) into bf16 hi pack + bf16 lo (residual) pack — extracts hi parts by bit ops
__device__ __forceinline__ void split2(float a, float b, uint32_t& hi, uint32_t& lo) {
    hi = pkbf(a, b);
    float ha = __uint_as_float(hi << 16);
    float hb = __uint_as_float(hi & 0xffff0000u);
    lo = pkbf(a - ha, b - hb);
}
__device__ __forceinline__ void mma_bf16(float* c, const uint32_t* a, uint32_t b0, uint32_t b1) {
    asm("mma.sync.aligned.m16n8k16.row.col.f32.bf16.bf16.f32 "
        "{%0,%1,%2,%3}, {%4,%5,%6,%7}, {%8,%9}, {%0,%1,%2,%3};"
        : "+f"(c[0]), "+f"(c[1]), "+f"(c[2]), "+f"(c[3])
        : "r"(a[0]), "r"(a[1]), "r"(a[2]), "r"(a[3]), "r"(b0), "r"(b1));
}

// ---------------- CSR build ----------------
__global__ void k_clear() {
    int i = blockIdx.x * blockDim.x + threadIdx.x;
    if (i < NN) g_cnt[i] = 0;
}
__global__ void k_hist(const int* __restrict__ dst) {
    int e = blockIdx.x * blockDim.x + threadIdx.x;
    if (e < NE) atomicAdd(&g_cnt[dst[e]], 1);
}
__global__ void k_dinv() {
    int i = blockIdx.x * blockDim.x + threadIdx.x;
    if (i < NN) g_dinv[i] = rsqrtf((float)g_cnt[i] + 1.0f);
}
__global__ __launch_bounds__(SCAN_B) void k_scan1() {
    __shared__ int sh[SCAN_B];
    int t = threadIdx.x;
    int i = blockIdx.x * SCAN_B + t;
    sh[t] = (i < NN) ? g_cnt[i] : 0;
    __syncthreads();
#pragma unroll
    for (int off = 1; off < SCAN_B; off <<= 1) {
        int v = (t >= off) ? sh[t - off] : 0;
        __syncthreads();
        sh[t] += v;
        __syncthreads();
    }
    if (i < NN) g_tmp[i] = sh[t];
    if (t == SCAN_B - 1) g_bsum[blockIdx.x] = sh[t];
}
__global__ __launch_bounds__(128) void k_scan2() {
    __shared__ int sh[128];
    int t = threadIdx.x;
    int v0 = (t < SCAN_NB) ? g_bsum[t] : 0;
    sh[t] = v0;
    __syncthreads();
#pragma unroll
    for (int off = 1; off < 128; off <<= 1) {
        int v = (t >= off) ? sh[t - off] : 0;
        __syncthreads();
        sh[t] += v;
        __syncthreads();
    }
    if (t < SCAN_NB) g_bsum[t] = sh[t] - v0;
}
__global__ void k_scan3() {
    int i = blockIdx.x * blockDim.x + threadIdx.x;
    if (i < NN) {
        g_rowstart[i + 1] = g_tmp[i] + g_bsum[i >> 10];
        if (i == 0) g_rowstart[0] = 0;
        g_cnt[i] = 0;
    }
}
__global__ void k_fill(const int* __restrict__ src, const int* __restrict__ dst) {
    int e = blockIdx.x * blockDim.x + threadIdx.x;
    if (e < NE) {
        int d = dst[e];
        int pos = g_rowstart[d] + atomicAdd(&g_cnt[d], 1);
        g_csrsrc[pos] = src[e];
    }
}

// ---------------- pack W1 [512,64] + W2 [64,256] into mma b-fragments ----------------
__global__ void k_packW(const float* __restrict__ B1, const float* __restrict__ B2) {
    int e = blockIdx.x * blockDim.x + threadIdx.x;
    if (e < 8192) {
        int l = e & 31, j = (e >> 5) & 7, s = e >> 8;
        int g = l >> 2, t = l & 3;
        int n = 8 * j + g;
        int k = 16 * s + 2 * t;
        float f0 = B1[(size_t)k * 64 + n];
        float f1 = B1[(size_t)(k + 1) * 64 + n];
        float f2 = B1[(size_t)(k + 8) * 64 + n];
        float f3 = B1[(size_t)(k + 9) * 64 + n];
        uint32_t h01, l01, h23, l23;
        split2(f0, f1, h01, l01);
        split2(f2, f3, h23, l23);
        g_bfrag[e] = make_uint4(h01, h23, l01, l23);
    } else if (e < 8192 + 4096) {
        int e2 = e - 8192;
        int l = e2 & 31, j = (e2 >> 5) & 31, s = e2 >> 10;
        int g = l >> 2, t = l & 3;
        int n = 8 * j + g;
        int k = 16 * s + 2 * t;
        float f0 = B2[(size_t)k * D2 + n];
        float f1 = B2[(size_t)(k + 1) * D2 + n];
        float f2 = B2[(size_t)(k + 8) * D2 + n];
        float f3 = B2[(size_t)(k + 9) * D2 + n];
        uint32_t h01, l01, h23, l23;
        split2(f0, f1, h01, l01);
        split2(f2, f3, h23, l23);
        g_bfrag2[e2] = make_uint4(h01, h23, l01, l23);
    }
}

// ---------------- GEMM1 via mma.sync bf16 split-3; writes UNSCALED bf16x2 ----------------
#define G1A_STRIDE 36
#define G1_SMEM_BYTES (2 * 256 * 72 * 2)
__global__ __launch_bounds__(256) void k_gemm1_mma(const float* __restrict__ A,
                                                   uint32_t* __restrict__ C) {
    extern __shared__ char smem[];
    uint32_t* Ah = (uint32_t*)smem;
    uint32_t* Al = (uint32_t*)(smem + 256 * 72 * 2);
    int tid  = threadIdx.x;
    int lane = tid & 31;
    int w    = tid >> 5;
    int g    = lane >> 2;
    int t    = lane & 3;
    int bm   = blockIdx.x * 256;

    float acc[2][8][4];
#pragma unroll
    for (int m = 0; m < 2; m++)
#pragma unroll
        for (int j = 0; j < 8; j++)
#pragma unroll
            for (int q = 0; q < 4; q++) acc[m][j][q] = 0.f;

    int lr = tid >> 4;
    int c4 = (tid & 15) * 4;

    for (int ch = 0; ch < 8; ch++) {
        int k0 = ch * 64;
#pragma unroll
        for (int i = 0; i < 16; i++) {
            int row  = lr + 16 * i;
            int grow = bm + row;
            float4 v = (grow < NN) ? *(const float4*)(A + (size_t)grow * FIN + k0 + c4)
                                   : make_float4(0.f, 0.f, 0.f, 0.f);
            uint32_t h01, l01, h23, l23;
            split2(v.x, v.y, h01, l01);
            split2(v.z, v.w, h23, l23);
            int idx = row * G1A_STRIDE + (c4 >> 1);
            *(uint2*)&Ah[idx] = make_uint2(h01, h23);
            *(uint2*)&Al[idx] = make_uint2(l01, l23);
        }
        __syncthreads();
#pragma unroll
        for (int s4 = 0; s4 < 4; s4++) {
            int kk = s4 * 16;
            int gs = ch * 4 + s4;
            uint32_t ah[2][4], al[2][4];
#pragma unroll
            for (int m = 0; m < 2; m++) {
                int r0 = w * 32 + m * 16 + g;
                int kc = (kk + 2 * t) >> 1;
                ah[m][0] = Ah[r0 * G1A_STRIDE + kc];
                ah[m][1] = Ah[(r0 + 8) * G1A_STRIDE + kc];
                ah[m][2] = Ah[r0 * G1A_STRIDE + kc + 4];
                ah[m][3] = Ah[(r0 + 8) * G1A_STRIDE + kc + 4];
                al[m][0] = Al[r0 * G1A_STRIDE + kc];
                al[m][1] = Al[(r0 + 8) * G1A_STRIDE + kc];
                al[m][2] = Al[r0 * G1A_STRIDE + kc + 4];
                al[m][3] = Al[(r0 + 8) * G1A_STRIDE + kc + 4];
            }
#pragma unroll
            for (int j = 0; j < 8; j++) {
                uint4 bf4 = __ldg(&g_bfrag[(gs * 8 + j) * 32 + lane]);
#pragma unroll
                for (int m = 0; m < 2; m++) {
                    mma_bf16(acc[m][j], ah[m], bf4.x, bf4.y);
                    mma_bf16(acc[m][j], ah[m], bf4.z, bf4.w);
                    mma_bf16(acc[m][j], al[m], bf4.x, bf4.y);
                }
            }
        }
        __syncthreads();
    }
#pragma unroll
    for (int m = 0; m < 2; m++) {
        int row = bm + w * 32 + m * 16 + g;
#pragma unroll
        for (int j = 0; j < 8; j++) {
            int cp = 4 * j + t;
            if (row < NN)
                C[(size_t)row * 32 + cp] = pkbf(acc[m][j][0], acc[m][j][1]);
            if (row + 8 < NN)
                C[(size_t)(row + 8) * 32 + cp] = pkbf(acc[m][j][2], acc[m][j][3]);
        }
    }
}

// ---------------- scale xw1 by dinv (in place, bf16) ----------------
__global__ void k_scale_xw1(uint32_t* __restrict__ xw1) {
    int i = blockIdx.x * blockDim.x + threadIdx.x;   // over NN*32 uint32s
    if (i >= NN * 32) return;
    float dd = g_dinv[i >> 5];
    float2 v = upbf(xw1[i]);
    xw1[i] = pkbf(v.x * dd, v.y * dd);
}

// ---------------- gather 1: bf16 in -> bf16 out (relu+bias, dinv^2 scaling), unroll 8 ----
__global__ __launch_bounds__(256) void k_gather_bf2bf(const uint32_t* __restrict__ in,
                                                      uint32_t* __restrict__ out,
                                                      const float* __restrict__ bias) {
    int node = (blockIdx.x * blockDim.x + threadIdx.x) >> 5;
    if (node >= NN) return;
    int lane = threadIdx.x & 31;
    float dd = g_dinv[node];
    float2 self = upbf(in[node * 32 + lane]);
    float ax = self.x, ay = self.y;
    int e   = g_rowstart[node];
    int end = g_rowstart[node + 1];
    for (; e + 7 < end; e += 8) {
        int s[8];
#pragma unroll
        for (int q = 0; q < 8; q++) s[q] = __ldg(&g_csrsrc[e + q]);
        float2 v[8];
#pragma unroll
        for (int q = 0; q < 8; q++) v[q] = upbf(__ldg(&in[s[q] * 32 + lane]));
#pragma unroll
        for (int q = 0; q < 8; q++) { ax += v[q].x; ay += v[q].y; }
    }
    for (; e + 3 < end; e += 4) {
        int s[4];
#pragma unroll
        for (int q = 0; q < 4; q++) s[q] = __ldg(&g_csrsrc[e + q]);
        float2 v[4];
#pragma unroll
        for (int q = 0; q < 4; q++) v[q] = upbf(__ldg(&in[s[q] * 32 + lane]));
#pragma unroll
        for (int q = 0; q < 4; q++) { ax += v[q].x; ay += v[q].y; }
    }
    for (; e < end; e++) {
        float2 v = upbf(__ldg(&in[__ldg(&g_csrsrc[e]) * 32 + lane]));
        ax += v.x;
        ay += v.y;
    }
    float2 bb = ((const float2*)bias)[lane];
    ax = fmaxf(ax * dd + bb.x, 0.f) * dd;
    ay = fmaxf(ay * dd + bb.y, 0.f) * dd;
    out[node * 32 + lane] = pkbf(ax, ay);
}

// ---------------- gather 2: bf16 in -> fp32 out (plain aggregate, dinv scale), unroll 8 ----
__global__ __launch_bounds__(256) void k_gather_bf2f(const uint32_t* __restrict__ in,
                                                     float* __restrict__ out) {
    int node = (blockIdx.x * blockDim.x + threadIdx.x) >> 5;
    if (node >= NN) return;
    int lane = threadIdx.x & 31;
    float dd = g_dinv[node];
    float2 self = upbf(in[node * 32 + lane]);
    float ax = self.x, ay = self.y;
    int e   = g_rowstart[node];
    int end = g_rowstart[node + 1];
    for (; e + 7 < end; e += 8) {
        int s[8];
#pragma unroll
        for (int q = 0; q < 8; q++) s[q] = __ldg(&g_csrsrc[e + q]);
        float2 v[8];
#pragma unroll
        for (int q = 0; q < 8; q++) v[q] = upbf(__ldg(&in[s[q] * 32 + lane]));
#pragma unroll
        for (int q = 0; q < 8; q++) { ax += v[q].x; ay += v[q].y; }
    }
    for (; e + 3 < end; e += 4) {
        int s[4];
#pragma unroll
        for (int q = 0; q < 4; q++) s[q] = __ldg(&g_csrsrc[e + q]);
        float2 v[4];
#pragma unroll
        for (int q = 0; q < 4; q++) v[q] = upbf(__ldg(&in[s[q] * 32 + lane]));
#pragma unroll
        for (int q = 0; q < 4; q++) { ax += v[q].x; ay += v[q].y; }
    }
    for (; e < end; e++) {
        float2 v = upbf(__ldg(&in[__ldg(&g_csrsrc[e]) * 32 + lane]));
        ax += v.x;
        ay += v.y;
    }
    ((float2*)(out + (size_t)node * 64))[lane] = make_float2(ax * dd, ay * dd);
}

// ---------------- GEMM2: one block per 256 rows, loops all 4 n-chunks; writes scaled z0 ----
__global__ __launch_bounds__(256) void k_gemm2_mma(const float* __restrict__ A,
                                                   const float* __restrict__ bias,
                                                   const float* __restrict__ W3) {
    extern __shared__ char smem[];
    uint32_t* Ah = (uint32_t*)smem;
    uint32_t* Al = (uint32_t*)(smem + 256 * 72 * 2);
    __shared__ float zpart[256];
    int tid  = threadIdx.x;
    int lane = tid & 31;
    int w    = tid >> 5;
    int g    = lane >> 2;
    int t    = lane & 3;
    int bm   = blockIdx.x * 256;
    zpart[tid] = 0.f;

    int lr = tid >> 4;
    int c4 = (tid & 15) * 4;
#pragma unroll
    for (int i = 0; i < 16; i++) {
        int row  = lr + 16 * i;
        int grow = bm + row;
        float4 v = (grow < NN) ? *(const float4*)(A + (size_t)grow * D1 + c4)
                               : make_float4(0.f, 0.f, 0.f, 0.f);
        uint32_t h01, l01, h23, l23;
        split2(v.x, v.y, h01, l01);
        split2(v.z, v.w, h23, l23);
        int idx = row * G1A_STRIDE + (c4 >> 1);
        *(uint2*)&Ah[idx] = make_uint2(h01, h23);
        *(uint2*)&Al[idx] = make_uint2(l01, l23);
    }
    __syncthreads();

    for (int c = 0; c < 4; c++) {
        float acc[2][8][4];
#pragma unroll
        for (int m = 0; m < 2; m++)
#pragma unroll
            for (int j = 0; j < 8; j++)
#pragma unroll
                for (int q = 0; q < 4; q++) acc[m][j][q] = 0.f;
#pragma unroll
        for (int s4 = 0; s4 < 4; s4++) {
            int kk = s4 * 16;
            uint32_t ah[2][4], al[2][4];
#pragma unroll
            for (int m = 0; m < 2; m++) {
                int r0 = w * 32 + m * 16 + g;
                int kc = (kk + 2 * t) >> 1;
                ah[m][0] = Ah[r0 * G1A_STRIDE + kc];
                ah[m][1] = Ah[(r0 + 8) * G1A_STRIDE + kc];
                ah[m][2] = Ah[r0 * G1A_STRIDE + kc + 4];
                ah[m][3] = Ah[(r0 + 8) * G1A_STRIDE + kc + 4];
                al[m][0] = Al[r0 * G1A_STRIDE + kc];
                al[m][1] = Al[(r0 + 8) * G1A_STRIDE + kc];
                al[m][2] = Al[r0 * G1A_STRIDE + kc + 4];
                al[m][3] = Al[(r0 + 8) * G1A_STRIDE + kc + 4];
            }
#pragma unroll
            for (int j = 0; j < 8; j++) {
                uint4 bf4 = __ldg(&g_bfrag2[(s4 * 32 + c * 8 + j) * 32 + lane]);
#pragma unroll
                for (int m = 0; m < 2; m++) {
                    mma_bf16(acc[m][j], ah[m], bf4.x, bf4.y);
                    mma_bf16(acc[m][j], ah[m], bf4.z, bf4.w);
                    mma_bf16(acc[m][j], al[m], bf4.x, bf4.y);
                }
            }
        }
#pragma unroll
        for (int m = 0; m < 2; m++) {
            int rl0 = w * 32 + m * 16 + g;
            float s0 = 0.f, s1 = 0.f;
#pragma unroll
            for (int j = 0; j < 8; j++) {
                int col = c * 64 + 8 * j + 2 * t;
                float b0 = bias[col], b1 = bias[col + 1];
                float w0 = W3[col],  w1 = W3[col + 1];
                s0 += fmaxf(acc[m][j][0] + b0, 0.f) * w0 + fmaxf(acc[m][j][1] + b1, 0.f) * w1;
                s1 += fmaxf(acc[m][j][2] + b0, 0.f) * w0 + fmaxf(acc[m][j][3] + b1, 0.f) * w1;
            }
            atomicAdd(&zpart[rl0],     s0);
            atomicAdd(&zpart[rl0 + 8], s1);
        }
    }
    __syncthreads();
    int row = bm + tid;
    if (row < NN) g_z0[row] = zpart[tid] * g_dinv[row];
}

// ---------------- fused z aggregation + BCE loss (z0 pre-scaled) ----------------
__global__ void k_zero(float* out) {
    if (blockIdx.x == 0 && threadIdx.x == 0) out[0] = 0.f;
}
__global__ __launch_bounds__(256) void k_zagg_loss(const float* __restrict__ b3,
                                                   const float* __restrict__ y,
                                                   float* __restrict__ out) {
    __shared__ float red[256];
    int i = blockIdx.x * blockDim.x + threadIdx.x;
    float v = 0.f;
    if (i < NN) {
        float dd  = g_dinv[i];
        float acc = g_z0[i];
        int e = g_rowstart[i], end = g_rowstart[i + 1];
        for (; e + 7 < end; e += 8) {
            int s[8];
#pragma unroll
            for (int q = 0; q < 8; q++) s[q] = __ldg(&g_csrsrc[e + q]);
            float vv = 0.f;
#pragma unroll
            for (int q = 0; q < 8; q++) vv += __ldg(&g_z0[s[q]]);
            acc += vv;
        }
        for (; e < end; e++) acc += __ldg(&g_z0[__ldg(&g_csrsrc[e])]);
        float z = acc * dd + b3[0];
        float t = y[i];
        v = fmaxf(z, 0.f) - z * t + log1pf(expf(-fabsf(z)));
    }
    red[threadIdx.x] = v;
    __syncthreads();
    for (int s = 128; s > 0; s >>= 1) {
        if (threadIdx.x < s) red[threadIdx.x] += red[threadIdx.x + s];
        __syncthreads();
    }
    if (threadIdx.x == 0) atomicAdd(out, red[0] * (1.0f / NN));
}

// ---------------- launcher ----------------
static cudaStream_t g_s2 = 0;
static cudaEvent_t  g_evFork = 0, g_evJoin = 0, g_evDinv = 0;

extern "C" void kernel_launch(void* const* d_in, const int* in_sizes, int n_in,
                              void* d_out, int out_size) {
    const float* x  = (const float*)d_in[0];
    const int*   ei = (const int*)  d_in[1];
    const float* y  = (const float*)d_in[2];
    const float* W1 = (const float*)d_in[3];
    const float* b1 = (const float*)d_in[4];
    const float* W2 = (const float*)d_in[5];
    const float* b2 = (const float*)d_in[6];
    const float* W3 = (const float*)d_in[7];
    const float* b3 = (const float*)d_in[8];
    const int* src = ei;
    const int* dst = ei + NE;
    float* out = (float*)d_out;

    uint32_t *p_xw1, *p_h1;
    float *p_ah1;
    cudaGetSymbolAddress((void**)&p_xw1, g_xw1);
    cudaGetSymbolAddress((void**)&p_h1,  g_h1);
    cudaGetSymbolAddress((void**)&p_ah1, g_ah1);

    cudaFuncSetAttribute(k_gemm1_mma, cudaFuncAttributeMaxDynamicSharedMemorySize, G1_SMEM_BYTES);
    cudaFuncSetAttribute(k_gemm2_mma, cudaFuncAttributeMaxDynamicSharedMemorySize, G1_SMEM_BYTES);

    if (!g_s2) {
        cudaStreamCreateWithFlags(&g_s2, cudaStreamNonBlocking);
        cudaEventCreateWithFlags(&g_evFork, cudaEventDisableTiming);
        cudaEventCreateWithFlags(&g_evJoin, cudaEventDisableTiming);
        cudaEventCreateWithFlags(&g_evDinv, cudaEventDisableTiming);
    }

    const int T = 256;
    // ---- fork at t=0: full CSR build on s2  ||  packW + gemm1 (unscaled) on default ----
    k_zero <<<1, 32>>>(out);
    cudaEventRecord(g_evFork, 0);
    cudaStreamWaitEvent(g_s2, g_evFork, 0);
    k_clear<<<(NN + T - 1) / T, T, 0, g_s2>>>();
    k_hist <<<(NE + T - 1) / T, T, 0, g_s2>>>(dst);
    k_dinv <<<(NN + T - 1) / T, T, 0, g_s2>>>();
    cudaEventRecord(g_evDinv, g_s2);
    k_scan1<<<SCAN_NB, SCAN_B, 0, g_s2>>>();
    k_scan2<<<1, 128, 0, g_s2>>>();
    k_scan3<<<(NN + T - 1) / T, T, 0, g_s2>>>();
    k_fill <<<(NE + T - 1) / T, T, 0, g_s2>>>(src, dst);
    cudaEventRecord(g_evJoin, g_s2);

    k_packW<<<48, 256>>>(W1, W2);
    k_gemm1_mma<<<(NN + 255) / 256, 256, G1_SMEM_BYTES>>>(x, p_xw1);

    // ---- scale xw1 as soon as dinv is ready (overlaps with k_fill on s2) ----
    cudaStreamWaitEvent(0, g_evDinv, 0);
    k_scale_xw1<<<(NN * 32 + T - 1) / T, T>>>(p_xw1);

    // ---- join with CSR build, then layer-1 aggregate ----
    cudaStreamWaitEvent(0, g_evJoin, 0);
    k_gather_bf2bf<<<(NN * 32 + T - 1) / T, T>>>(p_xw1, p_h1, b1);

    // ---- layer 2 + fused layer-3 matvec ----
    k_gather_bf2f<<<(NN * 32 + T - 1) / T, T>>>(p_h1, p_ah1);
    k_gemm2_mma<<<(NN + 255) / 256, 256, G1_SMEM_BYTES>>>(p_ah1, b2, W3);

    // ---- z aggregation + loss ----
    k_zagg_loss<<<(NN + T - 1) / T, T>>>(b3, y, out);
}